// round 6
// baseline (speedup 1.0000x reference)
#include <cuda_runtime.h>

// Problem constants (from reference)
#define BATCH   1024
#define NK      33          // ykinput rows = 33; nonzero support width (2*16+1)
#define COLBASE 4080        // VECCNTR - 1 - 15
#define VEC     8192
#define EPSF    0.01f

#define NBLOCKS 128         // one wave; best measured config (R3)
#define NTHREADS 256        // 8 warps per block, one warp per batch row
#define WPB     8

__device__ float        g_total = 0.0f;
__device__ unsigned int g_count = 0;

__global__ void __launch_bounds__(NTHREADS)
ngl_kernel(const float* __restrict__ input,
           const float* __restrict__ output,
           const float* __restrict__ ykinput,
           float* __restrict__ out)
{
    __shared__ float yk_s[NK * NK];     // yk_s[k*33 + j] = ykinput[k, 4080+j]
    __shared__ float a_s[WPB][64];      // per-warp coefficient exchange

    const int tid  = threadIdx.x;
    const int warp = tid >> 5;
    const int lane = tid & 31;
    const int row  = blockIdx.x * WPB + warp;   // one warp per batch row

    // ---- Per-row parameter loads (issue early, overlap with tile load) ----
    const float4 in4 = *reinterpret_cast<const float4*>(input + row * 4);
    const float p0 = in4.x, p1 = in4.y, p2 = in4.z;
    const int   m  = (int)in4.w;                // 1..16, exact in fp32
    const float o0 = output[row * 3 + 0];
    const float o1 = output[row * 3 + 1];
    const float o2 = output[row * 3 + 2];

    // ---- Vectorized load of the 33x33 live slice of ykinput ---------------
    // &ykinput[k*VEC + COLBASE] is 16B-aligned. 33 rows x (8 float4 + 1 float).
    for (int s = tid; s < NK * 9; s += NTHREADS) {
        const int k = s / 9;
        const int q = s - k * 9;
        const float* gsrc = ykinput + k * VEC + COLBASE;
        float* srow = &yk_s[k * NK];
        if (q < 8) {
            const float4 v = *reinterpret_cast<const float4*>(gsrc + 4 * q);
            srow[4 * q + 0] = v.x;
            srow[4 * q + 1] = v.y;
            srow[4 * q + 2] = v.z;
            srow[4 * q + 3] = v.w;
        } else {
            srow[32] = gsrc[32];
        }
    }

    // ---- Lane-distributed (m-1)-fold 3-tap convolution ---------------------
    // Shifted mapping: lane l owns e = c[2l-2], o = c[2l-1].
    // Support stays within c[0..32] (lanes 1..17); lane 0 holds c[-2],c[-1]=0
    // and lane 31 holds c[60],c[61]=0 forever, so shfl boundary self-values
    // are already correct zeros -> no predicates/selects on the chain.
    float e = 0.0f, o = 0.0f;
    if (lane == 8) { o = p0; }               // c[15]
    if (lane == 9) { e = p1; o = p2; }       // c[16], c[17]

    for (int t = 0; t < m - 1; ++t) {
        // Off-chain partials (independent of the shuffles):
        const float se = fmaf(p1, e, p2 * o);     // part of e_new
        const float so = fmaf(p0, e, p1 * o);     // part of o_new
        const float o_up = __shfl_up_sync(0xffffffffu, o, 1);   // c[2l-3]
        const float e_dn = __shfl_down_sync(0xffffffffu, e, 1); // c[2l]
        e = fmaf(p0, o_up, se);              // chain: shfl + 1 FMA
        o = fmaf(p2, e_dn, so);
    }

    a_s[warp][2 * lane]     = e;             // buf[j+2] = c[j]
    a_s[warp][2 * lane + 1] = o;
    __syncthreads();    // covers yk_s fill AND per-warp coefficient exchange

    // ---- Hoist coefficients into registers (broadcast LDS) -----------------
    float areg[NK];
    #pragma unroll
    for (int j = 0; j < NK; ++j) areg[j] = a_s[warp][j + 2];

    // ---- Lane-parallel over k: phim_y, psi_y, rational loss term -----------
    float lsum = 0.0f;
    for (int k = lane; k < NK; k += 32) {     // lane 0 also does k=32
        const float* y = &yk_s[k * NK];       // stride 33 across lanes: conflict-free
        float pa = 0.0f, pb = 0.0f;           // dual accumulators: halve dep chain
        #pragma unroll
        for (int j = 0; j < 32; j += 2) {
            pa = fmaf(areg[j],     y[j],     pa);
            pb = fmaf(areg[j + 1], y[j + 1], pb);
        }
        pa = fmaf(areg[32], y[32], pa);
        const float p = pa + pb;
        const float psi = fmaf(o0, y[15], fmaf(o1, y[16], o2 * y[17]));
        const float d = p - psi;
        const float q = 1.0f - p;
        lsum += __fdividef(d * d, fmaf(q, q, EPSF));
    }

    // ---- Per-warp reduction, then fire-and-forget RED into global total ----
    #pragma unroll
    for (int off = 16; off; off >>= 1)
        lsum += __shfl_down_sync(0xffffffffu, lsum, off);
    if (lane == 0) {
        atomicAdd(&g_total, lsum);            // no return use -> REDG
        __threadfence();                      // my add visible before block signals
    }
    __syncthreads();                          // all 8 warps' adds fenced

    // ---- Completion count; last block publishes the scalar -----------------
    if (tid == 0) {
        unsigned int old = atomicAdd(&g_count, 1u);
        if (old == (unsigned int)(NBLOCKS - 1)) {
            __threadfence();                  // acquire: all 1024 adds visible
            *out = *((volatile float*)&g_total);
            g_total = 0.0f;                   // re-arm for next graph replay
            g_count = 0u;
        }
    }
}

extern "C" void kernel_launch(void* const* d_in, const int* in_sizes, int n_in,
                              void* d_out, int out_size)
{
    const float* input   = (const float*)d_in[0];   // (1024, 4)
    const float* output  = (const float*)d_in[1];   // (1024, 3)
    const float* ykinput = (const float*)d_in[2];   // (33, 8192)
    float* out = (float*)d_out;                     // scalar loss
    (void)in_sizes; (void)n_in; (void)out_size;

    ngl_kernel<<<NBLOCKS, NTHREADS>>>(input, output, ykinput, out);
}

// round 7
// speedup vs baseline: 1.1107x; 1.1107x over previous
#include <cuda_runtime.h>

// Problem constants (from reference)
#define BATCH   1024
#define NK      33          // ykinput rows = 33; nonzero support width (2*16+1)
#define COLBASE 4080        // VECCNTR - 1 - 15
#define VEC     8192
#define EPSF    0.01f

#define NBLOCKS 128         // one wave; best measured config (R3)
#define NTHREADS 256        // 8 warps per block, one warp per batch row
#define WPB     8

__device__ float        g_total = 0.0f;
__device__ unsigned int g_count = 0;

__global__ void __launch_bounds__(NTHREADS)
ngl_kernel(const float* __restrict__ input,
           const float* __restrict__ output,
           const float* __restrict__ ykinput,
           float* __restrict__ out)
{
    __shared__ float yk_s[NK * NK];     // yk_s[k*33 + j] = ykinput[k, 4080+j]
    __shared__ float a_s[WPB][64];      // per-warp coefficient exchange
    __shared__ float wsum_s[WPB];

    const int tid  = threadIdx.x;
    const int warp = tid >> 5;
    const int lane = tid & 31;
    const int row  = blockIdx.x * WPB + warp;   // one warp per batch row

    // ---- Per-row parameter loads (issue early, overlap with tile load) ----
    const float4 in4 = *reinterpret_cast<const float4*>(input + row * 4);
    const float p0 = in4.x, p1 = in4.y, p2 = in4.z;
    const int   m  = (int)in4.w;                // 1..16, exact in fp32
    const float o0 = output[row * 3 + 0];
    const float o1 = output[row * 3 + 1];
    const float o2 = output[row * 3 + 2];

    // ---- Vectorized load of the 33x33 live slice of ykinput ---------------
    // &ykinput[k*VEC + COLBASE] is 16B-aligned. 33 rows x 8 float4 = 264
    // vector slots (shift/mask indexing, no integer division), plus a
    // 33-scalar tail column handled by the first 33 threads.
    for (int s = tid; s < NK * 8; s += NTHREADS) {
        const int k = s >> 3;
        const int q = s & 7;
        const float4 v = *reinterpret_cast<const float4*>(
            ykinput + k * VEC + COLBASE + 4 * q);
        float* srow = &yk_s[k * NK + 4 * q];
        srow[0] = v.x; srow[1] = v.y; srow[2] = v.z; srow[3] = v.w;
    }
    if (tid < NK)
        yk_s[tid * NK + 32] = ykinput[tid * VEC + COLBASE + 32];

    // ---- Lane-distributed (m-1)-fold 3-tap convolution ---------------------
    // Shifted mapping: lane l owns e = c[2l-2], o = c[2l-1].
    // Support stays within c[0..32] (lanes 1..17); lane 0 holds c[-2],c[-1]=0
    // and lane 31 holds c[60],c[61]=0 forever, so shfl boundary self-values
    // are already correct zeros -> no predicates/selects on the chain.
    float e = 0.0f, o = 0.0f;
    if (lane == 8) { o = p0; }               // c[15]
    if (lane == 9) { e = p1; o = p2; }       // c[16], c[17]

    for (int t = 0; t < m - 1; ++t) {
        const float se = fmaf(p1, e, p2 * o);     // off-chain partial of e_new
        const float so = fmaf(p0, e, p1 * o);     // off-chain partial of o_new
        const float o_up = __shfl_up_sync(0xffffffffu, o, 1);   // c[2l-3]
        const float e_dn = __shfl_down_sync(0xffffffffu, e, 1); // c[2l]
        e = fmaf(p0, o_up, se);              // chain: shfl + 1 FMA
        o = fmaf(p2, e_dn, so);
    }

    a_s[warp][2 * lane]     = e;             // buf[j+2] = c[j]
    a_s[warp][2 * lane + 1] = o;
    __syncthreads();    // covers yk_s fill AND per-warp coefficient exchange

    // ---- Hoist coefficients into registers (broadcast LDS) -----------------
    float areg[NK];
    #pragma unroll
    for (int j = 0; j < NK; ++j) areg[j] = a_s[warp][j + 2];

    // ---- Lane-parallel over k: phim_y, psi_y, rational loss term -----------
    float lsum = 0.0f;
    for (int k = lane; k < NK; k += 32) {     // lane 0 also does k=32
        const float* y = &yk_s[k * NK];       // stride 33 across lanes: conflict-free
        float pa = 0.0f, pb = 0.0f;           // dual accumulators: halve dep chain
        #pragma unroll
        for (int j = 0; j < 32; j += 2) {
            pa = fmaf(areg[j],     y[j],     pa);
            pb = fmaf(areg[j + 1], y[j + 1], pb);
        }
        pa = fmaf(areg[32], y[32], pa);
        const float p = pa + pb;
        const float psi = fmaf(o0, y[15], fmaf(o1, y[16], o2 * y[17]));
        const float d = p - psi;
        const float q = 1.0f - p;
        lsum += __fdividef(d * d, fmaf(q, q, EPSF));
    }

    // ---- Deterministic warp reduction --------------------------------------
    #pragma unroll
    for (int off = 16; off; off >>= 1)
        lsum += __shfl_down_sync(0xffffffffu, lsum, off);
    if (lane == 0)
        wsum_s[warp] = lsum;
    __syncthreads();

    // ---- One global atomic per block (measured-best tail, R3) --------------
    if (tid == 0) {
        float bs = 0.0f;
        #pragma unroll
        for (int w = 0; w < WPB; ++w) bs += wsum_s[w];
        atomicAdd(&g_total, bs);
        __threadfence();                      // release: my add before my count
        unsigned int old = atomicAdd(&g_count, 1u);
        if (old == (unsigned int)(NBLOCKS - 1)) {
            __threadfence();                  // acquire: all adds visible
            *out = *((volatile float*)&g_total);
            g_total = 0.0f;                   // re-arm for next graph replay
            g_count = 0u;
        }
    }
}

extern "C" void kernel_launch(void* const* d_in, const int* in_sizes, int n_in,
                              void* d_out, int out_size)
{
    const float* input   = (const float*)d_in[0];   // (1024, 4)
    const float* output  = (const float*)d_in[1];   // (1024, 3)
    const float* ykinput = (const float*)d_in[2];   // (33, 8192)
    float* out = (float*)d_out;                     // scalar loss
    (void)in_sizes; (void)n_in; (void)out_size;

    ngl_kernel<<<NBLOCKS, NTHREADS>>>(input, output, ykinput, out);
}